// round 1
// baseline (speedup 1.0000x reference)
#include <cuda_runtime.h>
#include <cuda_bf16.h>
#include <stdint.h>

#define NUM_ROWS 16384
#define HDIM     2048
#define KSEL     4
#define NEXP     64
#define NTOT     (NUM_ROWS * KSEL)   /* 65536 expanded slots */
#define NCHUNK   256
#define CHUNK    (NTOT / NCHUNK)     /* 256 items per chunk */

/* output layout (floats) */
#define X_OFF   0
#define RI_OFF  ((size_t)NTOT * HDIM)                 /* 134217728 */
#define CNT_OFF (RI_OFF + NTOT)                        /* +65536 */
#define SC_OFF  (CNT_OFF + NEXP)                       /* +64 */

/* scratch (no cudaMalloc allowed) */
__device__ int g_chunkCounts[NCHUNK * NEXP];  /* pass1: counts; pass2: bases */
__device__ int g_dest[NTOT];

/* ---- K1: per-chunk histogram ---- */
__global__ void k_hist(const int* __restrict__ eidx) {
    __shared__ int sh[NEXP];
    int t = threadIdx.x;
    if (t < NEXP) sh[t] = 0;
    __syncthreads();
    int i = blockIdx.x * CHUNK + t;
    int e = eidx[i];
    atomicAdd(&sh[e], 1);
    __syncthreads();
    if (t < NEXP) g_chunkCounts[blockIdx.x * NEXP + t] = sh[t];
}

/* ---- K2: totals, exclusive scan, per-chunk bases, counts output ---- */
__global__ void k_scan(float* __restrict__ out) {
    __shared__ int total[NEXP];
    __shared__ int offs[NEXP + 1];
    int e = threadIdx.x;   /* 64 threads */
    int s = 0;
    for (int c = 0; c < NCHUNK; ++c) s += g_chunkCounts[c * NEXP + e];
    total[e] = s;
    __syncthreads();
    if (e == 0) {
        int run = 0;
        for (int j = 0; j < NEXP; ++j) { offs[j] = run; run += total[j]; }
        offs[NEXP] = run;
    }
    __syncthreads();
    /* turn chunk counts into stable bases */
    int run = offs[e];
    for (int c = 0; c < NCHUNK; ++c) {
        int idx = c * NEXP + e;
        int v = g_chunkCounts[idx];
        g_chunkCounts[idx] = run;
        run += v;
    }
    out[CNT_OFF + e] = (float)total[e];
}

/* ---- K3: stable destination per slot + row_idx + scale outputs ---- */
__global__ void k_dest(const int* __restrict__ eidx,
                       const float* __restrict__ scale,
                       float* __restrict__ out) {
    int c = blockIdx.x * blockDim.x + threadIdx.x;  /* one chunk per thread */
    if (c >= NCHUNK) return;
    int base[NEXP];
#pragma unroll
    for (int j = 0; j < NEXP; ++j) base[j] = g_chunkCounts[c * NEXP + j];
    int i0 = c * CHUNK;
    for (int j = 0; j < CHUNK; ++j) {
        int i = i0 + j;
        int e = eidx[i];
        int d = base[e]++;
        g_dest[i] = d;
        out[RI_OFF + i] = (float)d;
        out[SC_OFF + d] = scale[i >> 2];
    }
}

/* ---- K4: big gather copy: expanded_x[dest[i]] = x[i/K] ---- */
__global__ void __launch_bounds__(128) k_copy(const float* __restrict__ x,
                                              float* __restrict__ out) {
    int i = blockIdx.x;          /* expanded slot 0..NTOT-1 */
    int src = i >> 2;            /* i / KSEL */
    int d = g_dest[i];
    const float4* __restrict__ s = (const float4*)(x + (size_t)src * HDIM);
    float4* __restrict__ o = (float4*)(out + X_OFF + (size_t)d * HDIM);
#pragma unroll
    for (int j = 0; j < 4; ++j) {
        int idx = threadIdx.x + j * 128;   /* 512 float4 per row */
        o[idx] = s[idx];
    }
}

extern "C" void kernel_launch(void* const* d_in, const int* in_sizes, int n_in,
                              void* d_out, int out_size) {
    const float* x     = (const float*)d_in[0];
    const int*   eidx  = (const int*)d_in[1];
    const float* scale = (const float*)d_in[2];
    float* out = (float*)d_out;

    k_hist<<<NCHUNK, CHUNK>>>(eidx);
    k_scan<<<1, NEXP>>>(out);
    k_dest<<<1, NCHUNK>>>(eidx, scale, out);
    k_copy<<<NTOT, 128>>>(x, out);
}

// round 2
// speedup vs baseline: 3.1012x; 3.1012x over previous
#include <cuda_runtime.h>
#include <cuda_bf16.h>
#include <stdint.h>

#define NUM_ROWS 16384
#define HDIM     2048
#define KSEL     4
#define NEXP     64
#define NTOT     (NUM_ROWS * KSEL)   /* 65536 expanded slots */
#define NCHUNK   256
#define CHUNK    (NTOT / NCHUNK)     /* 256 items per chunk */
#define NWARP    (CHUNK / 32)        /* 8 warps per chunk block */

/* output layout (floats) */
#define X_OFF   0
#define RI_OFF  ((size_t)NTOT * HDIM)                 /* 134217728 */
#define CNT_OFF (RI_OFF + NTOT)                        /* +65536 */
#define SC_OFF  (CNT_OFF + NEXP)                       /* +64 */

/* scratch (no cudaMalloc allowed) */
__device__ int g_chunkCounts[NCHUNK * NEXP];  /* pass1: counts; pass2: bases */
__device__ int g_dest[NTOT];

/* ---- K1: per-chunk histogram ---- */
__global__ void k_hist(const int* __restrict__ eidx) {
    __shared__ int sh[NEXP];
    int t = threadIdx.x;
    if (t < NEXP) sh[t] = 0;
    __syncthreads();
    int i = blockIdx.x * CHUNK + t;
    int e = eidx[i];
    atomicAdd(&sh[e], 1);
    __syncthreads();
    if (t < NEXP) g_chunkCounts[blockIdx.x * NEXP + t] = sh[t];
}

/* ---- K2: totals, exclusive scan, per-chunk bases, counts output ---- */
__global__ void k_scan(float* __restrict__ out) {
    __shared__ int total[NEXP];
    __shared__ int offs[NEXP + 1];
    int e = threadIdx.x;   /* 64 threads */
    int s = 0;
#pragma unroll 8
    for (int c = 0; c < NCHUNK; ++c) s += g_chunkCounts[c * NEXP + e];
    total[e] = s;
    __syncthreads();
    if (e == 0) {
        int run = 0;
        for (int j = 0; j < NEXP; ++j) { offs[j] = run; run += total[j]; }
        offs[NEXP] = run;
    }
    __syncthreads();
    /* turn chunk counts into stable bases */
    int run = offs[e];
    for (int c = 0; c < NCHUNK; ++c) {
        int idx = c * NEXP + e;
        int v = g_chunkCounts[idx];
        g_chunkCounts[idx] = run;
        run += v;
    }
    out[CNT_OFF + e] = (float)total[e];
}

/* ---- K3: stable destination per slot (parallel, match-based rank) ---- */
__global__ void __launch_bounds__(CHUNK) k_dest(const int* __restrict__ eidx,
                                                const float* __restrict__ scale,
                                                float* __restrict__ out) {
    __shared__ int shcnt[NWARP][NEXP];
    int t = threadIdx.x;
    int c = blockIdx.x;
    int w = t >> 5, lane = t & 31;

    for (int j = t; j < NWARP * NEXP; j += CHUNK)
        ((int*)shcnt)[j] = 0;
    __syncthreads();

    int i = c * CHUNK + t;
    int e = eidx[i];
    unsigned m = __match_any_sync(0xffffffffu, e);
    int rank = __popc(m & ((1u << lane) - 1));
    if (rank == 0) shcnt[w][e] = __popc(m);
    __syncthreads();

    int off = 0;
#pragma unroll
    for (int w2 = 0; w2 < NWARP; ++w2)
        if (w2 < w) off += shcnt[w2][e];

    int d = g_chunkCounts[c * NEXP + e] + off + rank;
    g_dest[i] = d;
    out[RI_OFF + i] = (float)d;
    out[SC_OFF + d] = scale[i >> 2];
}

/* ---- K4: big gather copy: expanded_x[dest[i]] = x[i/K] ---- */
__global__ void __launch_bounds__(128) k_copy(const float* __restrict__ x,
                                              float* __restrict__ out) {
    int i = blockIdx.x;          /* expanded slot 0..NTOT-1 */
    int src = i >> 2;            /* i / KSEL */
    int d = g_dest[i];
    const float4* __restrict__ s = (const float4*)(x + (size_t)src * HDIM);
    float4* __restrict__ o = (float4*)(out + X_OFF + (size_t)d * HDIM);
#pragma unroll
    for (int j = 0; j < 4; ++j) {
        int idx = threadIdx.x + j * 128;   /* 512 float4 per row */
        o[idx] = s[idx];
    }
}

extern "C" void kernel_launch(void* const* d_in, const int* in_sizes, int n_in,
                              void* d_out, int out_size) {
    const float* x     = (const float*)d_in[0];
    const int*   eidx  = (const int*)d_in[1];
    const float* scale = (const float*)d_in[2];
    float* out = (float*)d_out;

    k_hist<<<NCHUNK, CHUNK>>>(eidx);
    k_scan<<<1, NEXP>>>(out);
    k_dest<<<NCHUNK, CHUNK>>>(eidx, scale, out);
    k_copy<<<NTOT, 128>>>(x, out);
}